// round 10
// baseline (speedup 1.0000x reference)
#include <cuda_runtime.h>
#include <cuda_fp16.h>
#include <cstdint>
#include <cstddef>

// ResidualVectorQuantizer via warp-level fp16 MMA, 3-term exact-enough fp32 GEMM.
// R10: R9 base + negated-B prep (no negation in A-split) + packed half2 A-split
//      + zero-C MMA chain heads with cn moved to epilogue + unroll-2 n-tile loop.
// N x D points, L layers of NE codes (D=32, NE=256, L=4).
// Out (float32): x_q [N*D], mean_loss [1], indices [N*L].

#define DD   32
#define NEC  256
#define LL   4
#define TM   128
#define RVQ_BETA 0.25f
#define MAXBLK_P 8192

// ---- global scratch ----
// B pack per code: 32 words (128B), 8 chunks of 16B, values NEGATED:
//   chunk 2*kk = h b-frag words for kk; chunk 2*kk+1 = l b-frag words for kk
__device__ uint32_t g_bp[LL * NEC * 32];
__device__ float    g_cn[LL * NEC];          // 0.5*||c||^2
__device__ float    g_part[MAXBLK_P * LL];
__device__ unsigned g_ctr;

// ---- smem map (bytes) ----
#define OFF_B    0          // 256 codes * 128B swizzled = 32768
#define OFF_A    14336      // A rows alias B codes 112..255: 128*144=18432 -> ends 32768
                            // warp w's A rows = codes 112+36w..147+36w (exact per-warp partition)
#define OFF_R    32768      // residual 128*144 = 18432
#define OFF_CN   51200      // 1024 (current layer cn, fp32)
#define OFF_ARG  52224      // 512
#define OFF_RED  52736      // 1024
#define OFF_FLAG 53760
#define SMEM_BYTES 53888

__device__ __forceinline__ uint32_t h2u(__half2 h) { return *(uint32_t*)&h; }
__device__ __forceinline__ uint32_t packh2(__half a, __half b) {
    __half2 h = __halves2half2(a, b);
    return *(uint32_t*)&h;
}
__device__ __forceinline__ void sp16(float v, __half& h, __half& l) {
    h = __float2half_rn(v);
    l = __float2half_rn(v - __half2float(h));
}
__device__ __forceinline__ uint32_t smem_u32(const void* p) {
    uint32_t a;
    asm("{ .reg .u64 t; cvta.to.shared.u64 t, %1; cvt.u32.u64 %0, t; }" : "=r"(a) : "l"(p));
    return a;
}
__device__ __forceinline__ void cpasync16(uint32_t dst, const void* src) {
    asm volatile("cp.async.cg.shared.global [%0], [%1], 16;" :: "r"(dst), "l"(src));
}
#define CP_COMMIT() asm volatile("cp.async.commit_group;" ::: "memory")
#define CP_WAITALL() asm volatile("cp.async.wait_all;" ::: "memory")

// accumulate: D = A*B + D
#define MMA16(C, A0, A1, A2, A3, B0, B1) \
    asm volatile("mma.sync.aligned.m16n8k16.row.col.f32.f16.f16.f32 " \
        "{%0,%1,%2,%3}, {%4,%5,%6,%7}, {%8,%9}, {%0,%1,%2,%3};" \
        : "+f"((C)[0]), "+f"((C)[1]), "+f"((C)[2]), "+f"((C)[3]) \
        : "r"(A0), "r"(A1), "r"(A2), "r"(A3), "r"(B0), "r"(B1))

// chain head: D = A*B + 0 (constant-zero C; no MOV splat, no cn dependency)
#define MMA16_Z(C, A0, A1, A2, A3, B0, B1) \
    asm volatile("mma.sync.aligned.m16n8k16.row.col.f32.f16.f16.f32 " \
        "{%0,%1,%2,%3}, {%4,%5,%6,%7}, {%8,%9}, {%10,%10,%10,%10};" \
        : "=f"((C)[0]), "=f"((C)[1]), "=f"((C)[2]), "=f"((C)[3]) \
        : "r"(A0), "r"(A1), "r"(A2), "r"(A3), "r"(B0), "r"(B1), "f"(0.0f))

// ---------------- prep: pack NEGATED codebook splits + half-norms ----------------
__global__ void rvq_prep(const float* __restrict__ cb) {
    int e = blockIdx.x * blockDim.x + threadIdx.x;
    if (e >= LL * NEC) return;
    const float* row = cb + (size_t)e * DD;
    __half h[DD], lo[DD];
    float cn = 0.f;
    #pragma unroll
    for (int k = 0; k < DD; k++) {
        float v = row[k];
        sp16(-v, h[k], lo[k]);          // store negated splits
        cn = fmaf(v, v, cn);
    }
    g_cn[e] = 0.5f * cn;
    uint32_t* dst = g_bp + (size_t)e * 32;
    #pragma unroll
    for (int kk = 0; kk < 4; kk++) {
        dst[8*kk + 0] = packh2(h[2*kk],       h[2*kk + 1]);
        dst[8*kk + 1] = packh2(h[2*kk + 8],   h[2*kk + 9]);
        dst[8*kk + 2] = packh2(h[16 + 2*kk],  h[16 + 2*kk + 1]);
        dst[8*kk + 3] = packh2(h[24 + 2*kk],  h[24 + 2*kk + 1]);
        dst[8*kk + 4] = packh2(lo[2*kk],      lo[2*kk + 1]);
        dst[8*kk + 5] = packh2(lo[2*kk + 8],  lo[2*kk + 9]);
        dst[8*kk + 6] = packh2(lo[16 + 2*kk], lo[16 + 2*kk + 1]);
        dst[8*kk + 7] = packh2(lo[24 + 2*kk], lo[24 + 2*kk + 1]);
    }
}

// ---------------- main ----------------
__global__ void __launch_bounds__(TM, 4) rvq_mma_kernel(
    const float* __restrict__ x, const float* __restrict__ cb,
    float* __restrict__ out, int N, int has_loss, int has_idx, int nblk)
{
    extern __shared__ char smem[];
    const uint32_t sbase = smem_u32(smem);
    const int tid = threadIdx.x;
    const int w = tid >> 5;
    const int lane = tid & 31;
    const int q = lane >> 2;
    const int kk = lane & 3;
    const int p = blockIdx.x * TM + tid;
    const bool active = (p < N);

    char* rrow = smem + OFF_R + tid * 144;

    // init residual rows
    {
        float4* rp = (float4*)rrow;
        if (active) {
            const float4* xr = (const float4*)(x + (size_t)p * DD);
            #pragma unroll
            for (int j = 0; j < 8; j++) rp[j] = xr[j];
        } else {
            float4 z = make_float4(0.f, 0.f, 0.f, 0.f);
            #pragma unroll
            for (int j = 0; j < 8; j++) rp[j] = z;
        }
    }

    // swizzled B read offsets for this thread (within a code row)
    const uint32_t bhOff = OFF_B + (uint32_t)q * 128 + (uint32_t)(((2*kk)     ^ q) * 16);
    const uint32_t blOff = OFF_B + (uint32_t)q * 128 + (uint32_t)(((2*kk + 1) ^ q) * 16);

    float tl[LL];
    int bia[LL];

    for (int l = 0; l < LL; l++) {
        __syncthreads();   // entry: ALL warps done computing on previous B

        // ---- phase1: cp.async codes 0..111 (+ cn); doesn't touch A region ----
        {
            const char* src = (const char*)(g_bp + (size_t)(l * 256) * 32);
            #pragma unroll
            for (int i = tid; i < 896; i += TM) {
                int code = i >> 3, c = i & 7;
                cpasync16(sbase + OFF_B + code * 128 + ((c ^ (code & 7)) * 16), src + (size_t)i * 16);
            }
            const char* csrc = (const char*)(g_cn + (size_t)l * 256);
            if (tid < 64) cpasync16(sbase + OFF_CN + tid * 16, csrc + (size_t)tid * 16);
            CP_COMMIT();
        }

        // ---- A = residual fp16 splits -> OFF_A (packed half2 path; no negation) ----
        {
            float t[DD];
            const float4* rp = (const float4*)rrow;
            #pragma unroll
            for (int j = 0; j < 8; j++) {
                float4 v = rp[j];
                t[4*j] = v.x; t[4*j+1] = v.y; t[4*j+2] = v.z; t[4*j+3] = v.w;
            }
            char* ap = smem + OFF_A + tid * 144;
            #pragma unroll
            for (int c4 = 0; c4 < 4; c4++) {
                float2 va = make_float2(t[2*c4],      t[2*c4 + 1]);
                float2 vb = make_float2(t[2*c4 + 8],  t[2*c4 + 9]);
                float2 vc = make_float2(t[16 + 2*c4], t[16 + 2*c4 + 1]);
                float2 vd = make_float2(t[24 + 2*c4], t[24 + 2*c4 + 1]);
                __half2 ha = __float22half2_rn(va);
                __half2 hb = __float22half2_rn(vb);
                __half2 hc = __float22half2_rn(vc);
                __half2 hd = __float22half2_rn(vd);
                float2 fa = __half22float2(ha);
                float2 fb = __half22float2(hb);
                float2 fc = __half22float2(hc);
                float2 fd = __half22float2(hd);
                __half2 la = __float22half2_rn(make_float2(va.x - fa.x, va.y - fa.y));
                __half2 lb = __float22half2_rn(make_float2(vb.x - fb.x, vb.y - fb.y));
                __half2 lc = __float22half2_rn(make_float2(vc.x - fc.x, vc.y - fc.y));
                __half2 ld = __float22half2_rn(make_float2(vd.x - fd.x, vd.y - fd.y));
                *(uint4*)(ap + c4 * 16)      = make_uint4(h2u(ha), h2u(hb), h2u(hc), h2u(hd));
                *(uint4*)(ap + 64 + c4 * 16) = make_uint4(h2u(la), h2u(lb), h2u(lc), h2u(ld));
            }
        }
        __syncwarp();      // warp's A rows visible to warp's own frag loads

        // ---- A fragments (resident for the layer); reads ONLY this warp's rows ----
        uint4 U0h[2], U1h[2], U0l[2], U1l[2];
        {
            const char* ab = smem + OFF_A + (size_t)(w * 32 + q) * 144 + kk * 16;
            #pragma unroll
            for (int m = 0; m < 2; m++) {
                U0h[m] = *(const uint4*)(ab + (m * 16) * 144);
                U1h[m] = *(const uint4*)(ab + (m * 16 + 8) * 144);
                U0l[m] = *(const uint4*)(ab + (m * 16) * 144 + 64);
                U1l[m] = *(const uint4*)(ab + (m * 16 + 8) * 144 + 64);
            }
        }
        __syncwarp();      // all lanes done reading A -> warp's A area reusable

        // ---- phase2: each warp restages EXACTLY the 36 codes aliasing ITS OWN A rows ----
        {
            const char* src = (const char*)(g_bp + (size_t)(l * 256) * 32);
            int base = 896 + 288 * w + lane;
            #pragma unroll
            for (int t = 0; t < 9; t++) {
                int i = base + 32 * t;
                int code = i >> 3, c = i & 7;
                cpasync16(sbase + OFF_B + code * 128 + ((c ^ (code & 7)) * 16), src + (size_t)i * 16);
            }
            CP_COMMIT();
        }
        CP_WAITALL();
        __syncthreads();   // full B + cn staged across all warps

        float best[4];
        int bidx[4];
        #pragma unroll
        for (int j = 0; j < 4; j++) { best[j] = 3.402823466e38f; bidx[j] = 0; }

        // ---- one uninterrupted pass over all 32 n-tiles, ILP-2 pairing ----
        #pragma unroll 2
        for (int nt2 = 0; nt2 < 16; nt2++) {
            const char* p0 = smem + (size_t)nt2 * 2048;
            uint4 BH0 = *(const uint4*)(p0 + bhOff);
            uint4 BL0 = *(const uint4*)(p0 + blOff);
            uint4 BH1 = *(const uint4*)(p0 + 1024 + bhOff);
            uint4 BL1 = *(const uint4*)(p0 + 1024 + blOff);
            float2 cn0 = *(const float2*)(smem + OFF_CN + (size_t)(nt2 * 16 + kk * 2) * 4);
            float2 cn1 = *(const float2*)(smem + OFF_CN + (size_t)(nt2 * 16 + 8 + kk * 2) * 4);

            float C0[2][4], C1[2][4];
            // chain heads: D = A*B + 0 (no cn dependency, no MOV splat)
            #pragma unroll
            for (int m = 0; m < 2; m++) {
                MMA16_Z(C0[m], U0h[m].x, U1h[m].x, U0h[m].y, U1h[m].y, BH0.x, BH0.y);
                MMA16_Z(C1[m], U0h[m].x, U1h[m].x, U0h[m].y, U1h[m].y, BH1.x, BH1.y);
            }
            #pragma unroll
            for (int m = 0; m < 2; m++) {
                MMA16(C0[m], U0h[m].z, U1h[m].z, U0h[m].w, U1h[m].w, BH0.z, BH0.w);
                MMA16(C1[m], U0h[m].z, U1h[m].z, U0h[m].w, U1h[m].w, BH1.z, BH1.w);
            }
            #pragma unroll
            for (int m = 0; m < 2; m++) {
                MMA16(C0[m], U0l[m].x, U1l[m].x, U0l[m].y, U1l[m].y, BH0.x, BH0.y);
                MMA16(C1[m], U0l[m].x, U1l[m].x, U0l[m].y, U1l[m].y, BH1.x, BH1.y);
            }
            #pragma unroll
            for (int m = 0; m < 2; m++) {
                MMA16(C0[m], U0l[m].z, U1l[m].z, U0l[m].w, U1l[m].w, BH0.z, BH0.w);
                MMA16(C1[m], U0l[m].z, U1l[m].z, U0l[m].w, U1l[m].w, BH1.z, BH1.w);
            }
            #pragma unroll
            for (int m = 0; m < 2; m++) {
                MMA16(C0[m], U0h[m].x, U1h[m].x, U0h[m].y, U1h[m].y, BL0.x, BL0.y);
                MMA16(C1[m], U0h[m].x, U1h[m].x, U0h[m].y, U1h[m].y, BL1.x, BL1.y);
            }
            #pragma unroll
            for (int m = 0; m < 2; m++) {
                MMA16(C0[m], U0h[m].z, U1h[m].z, U0h[m].w, U1h[m].w, BL0.z, BL0.w);
                MMA16(C1[m], U0h[m].z, U1h[m].z, U0h[m].w, U1h[m].w, BL1.z, BL1.w);
            }

            int nb0 = (nt2 * 16) + kk * 2;
            int nb1 = nb0 + 8;
            #pragma unroll
            for (int m = 0; m < 2; m++)
                #pragma unroll
                for (int hi = 0; hi < 2; hi++) {
                    int jj = m * 2 + hi;
                    {
                        float s0 = C0[m][hi*2]     + cn0.x;
                        float s1 = C0[m][hi*2 + 1] + cn0.y;
                        float mn = fminf(s0, s1);
                        int cand = (s1 < s0) ? (nb0 + 1) : nb0;
                        bidx[jj] = (mn < best[jj]) ? cand : bidx[jj];
                        best[jj] = fminf(best[jj], mn);
                    }
                    {
                        float s0 = C1[m][hi*2]     + cn1.x;
                        float s1 = C1[m][hi*2 + 1] + cn1.y;
                        float mn = fminf(s0, s1);
                        int cand = (s1 < s0) ? (nb1 + 1) : nb1;
                        bidx[jj] = (mn < best[jj]) ? cand : bidx[jj];
                        best[jj] = fminf(best[jj], mn);
                    }
                }
        }

        // ---- argmin reduce across the 4 kk-lanes of each group ----
        #pragma unroll
        for (int jj = 0; jj < 4; jj++) {
            #pragma unroll
            for (int ofs = 1; ofs <= 2; ofs <<= 1) {
                float ob = __shfl_xor_sync(0xffffffffu, best[jj], ofs);
                int oi = __shfl_xor_sync(0xffffffffu, bidx[jj], ofs);
                if (ob < best[jj] || (ob == best[jj] && oi < bidx[jj])) {
                    best[jj] = ob; bidx[jj] = oi;
                }
            }
        }
        int* argb = (int*)(smem + OFF_ARG);
        if (kk == 0) {
            #pragma unroll
            for (int jj = 0; jj < 4; jj++)
                argb[w * 32 + (jj >> 1) * 16 + (jj & 1) * 8 + q] = bidx[jj];
        }
        __syncwarp();
        int bi = argb[w * 32 + lane];
        bia[l] = bi;

        // ---- residual update + loss (exact fp op order of the reference) ----
        {
            const float4* cg = (const float4*)(cb + ((size_t)l * NEC + bi) * DD);
            float4* rp = (float4*)rrow;
            float ls = 0.f;
            #pragma unroll
            for (int j = 0; j < 8; j++) {
                float4 c = cg[j];
                float4 rv = rp[j];
                float t0, xres;
                t0 = c.x - rv.x; ls = fmaf(t0, t0, ls); xres = rv.x + t0; rv.x = rv.x - xres;
                t0 = c.y - rv.y; ls = fmaf(t0, t0, ls); xres = rv.y + t0; rv.y = rv.y - xres;
                t0 = c.z - rv.z; ls = fmaf(t0, t0, ls); xres = rv.z + t0; rv.z = rv.z - xres;
                t0 = c.w - rv.w; ls = fmaf(t0, t0, ls); xres = rv.w + t0; rv.w = rv.w - xres;
                rp[j] = rv;
            }
            tl[l] = active ? ls : 0.f;
        }
    }

    // ---- outputs ----
    if (active) {
        const float4* xr = (const float4*)(x + (size_t)p * DD);
        float4* qo = (float4*)(out + (size_t)p * DD);
        const float4* rp = (const float4*)rrow;
        #pragma unroll
        for (int j = 0; j < 8; j++) {
            float4 v = xr[j];
            float4 rv = rp[j];
            float4 qv;
            qv.x = v.x - rv.x; qv.y = v.y - rv.y;
            qv.z = v.z - rv.z; qv.w = v.w - rv.w;
            qo[j] = qv;
        }
        if (has_idx) {
            float* oi = out + (size_t)N * DD + (has_loss ? 1 : 0) + (size_t)p * LL;
            #pragma unroll
            for (int l = 0; l < LL; l++) oi[l] = (float)bia[l];
        }
    }

    // ---- per-block loss partials: warp shuffle reduce (deterministic order) ----
    {
        float* wsum = (float*)(smem + OFF_RED);
        #pragma unroll
        for (int l = 0; l < LL; l++) {
            float v = tl[l];
            v += __shfl_xor_sync(0xffffffffu, v, 16);
            v += __shfl_xor_sync(0xffffffffu, v, 8);
            v += __shfl_xor_sync(0xffffffffu, v, 4);
            v += __shfl_xor_sync(0xffffffffu, v, 2);
            v += __shfl_xor_sync(0xffffffffu, v, 1);
            if (lane == 0) wsum[w * LL + l] = v;
        }
        __syncthreads();
        if (tid < LL) {
            float s = ((wsum[tid] + wsum[LL + tid]) + (wsum[2*LL + tid] + wsum[3*LL + tid]));
            g_part[(size_t)blockIdx.x * LL + tid] = s;
        }
        __threadfence();
        __syncthreads();
    }

    // ---- last block finalizes loss, resets ctr ----
    unsigned* flag = (unsigned*)(smem + OFF_FLAG);
    if (tid == 0) {
        unsigned done = atomicAdd(&g_ctr, 1u);
        *flag = (done == (unsigned)(nblk - 1)) ? 1u : 0u;
    }
    __syncthreads();
    if (*flag) {
        __threadfence();
        double acc = 0.0;
        for (int b = tid; b < nblk; b += TM) {
            #pragma unroll
            for (int l = 0; l < LL; l++) acc += (double)g_part[(size_t)b * LL + l];
        }
        double* dred = (double*)(smem + OFF_RED);
        dred[tid] = acc;
        __syncthreads();
        #pragma unroll
        for (int s = TM / 2; s > 0; s >>= 1) {
            if (tid < s) dred[tid] += dred[tid + s];
            __syncthreads();
        }
        if (tid == 0) {
            if (has_loss) {
                double wgt = (1.0 + (double)RVQ_BETA) / ((double)N * (double)DD * (double)LL);
                out[(size_t)N * DD] = (float)(dred[0] * wgt);
            }
            g_ctr = 0u;
        }
    }
}

extern "C" void kernel_launch(void* const* d_in, const int* in_sizes, int n_in,
                              void* d_out, int out_size) {
    const float* x;
    const float* cb;
    int nx;
    if (n_in >= 2 && in_sizes[0] >= in_sizes[1]) {
        x = (const float*)d_in[0]; cb = (const float*)d_in[1]; nx = in_sizes[0];
    } else {
        x = (const float*)d_in[1]; cb = (const float*)d_in[0]; nx = in_sizes[1];
    }
    int N = nx / DD;
    float* out = (float*)d_out;

    long long need_full = (long long)N * DD + 1 + (long long)N * LL;
    int has_loss = (out_size > (long long)N * DD) ? 1 : 0;
    int has_idx  = (out_size >= need_full) ? 1 : 0;

    int nblk = (N + TM - 1) / TM;
    if (nblk > MAXBLK_P) nblk = MAXBLK_P;

    cudaFuncSetAttribute(rvq_mma_kernel, cudaFuncAttributeMaxDynamicSharedMemorySize, SMEM_BYTES);

    rvq_prep<<<(LL * NEC + 127) / 128, 128>>>(cb);
    rvq_mma_kernel<<<nblk, TM, SMEM_BYTES>>>(x, cb, out, N, has_loss, has_idx, nblk);
}

// round 11
// speedup vs baseline: 1.0652x; 1.0652x over previous
#include <cuda_runtime.h>
#include <cuda_fp16.h>
#include <cstdint>
#include <cstddef>

// ResidualVectorQuantizer via warp-level fp16 MMA, 3-term exact-enough fp32 GEMM.
// R11: R9 base (compute loop frozen, unroll 2) + residual-update gather from SMEM
//      (c = h+l reconstruction; no L2 gather) + split-wait staging (phase-1 compute
//      overlaps phase-2 cp.async landing).
// N x D points, L layers of NE codes (D=32, NE=256, L=4).
// Out (float32): x_q [N*D], mean_loss [1], indices [N*L].

#define DD   32
#define NEC  256
#define LL   4
#define TM   128
#define RVQ_BETA 0.25f
#define MAXBLK_P 8192

// ---- global scratch ----
// B pack per code: 32 words (128B), 8 chunks of 16B (positive values):
//   chunk 2*kk = h b-frag words for kk; chunk 2*kk+1 = l b-frag words for kk
//   word t of chunk 2*kk: pairs (2kk,2kk+1),(2kk+8,2kk+9),(16+2kk,17+2kk),(24+2kk,25+2kk)
__device__ uint32_t g_bp[LL * NEC * 32];
__device__ float    g_cn[LL * NEC];          // 0.5*||c||^2
__device__ float    g_part[MAXBLK_P * LL];
__device__ unsigned g_ctr;

// ---- smem map (bytes) ----
#define OFF_B    0          // 256 codes * 128B swizzled = 32768
#define OFF_A    14336      // A rows alias B codes 112..255: 128*144=18432 -> ends 32768
                            // warp w's A rows = codes 112+36w..147+36w (exact per-warp partition)
#define OFF_R    32768      // residual 128*144 = 18432
#define OFF_CN   51200      // 1024 (current layer cn, fp32)
#define OFF_ARG  52224      // 512
#define OFF_RED  52736      // 1024
#define OFF_FLAG 53760
#define SMEM_BYTES 53888

__device__ __forceinline__ uint32_t packh2(__half a, __half b) {
    __half2 h = __halves2half2(a, b);
    return *(uint32_t*)&h;
}
__device__ __forceinline__ void sp16(float v, __half& h, __half& l) {
    h = __float2half_rn(v);
    l = __float2half_rn(v - __half2float(h));
}
__device__ __forceinline__ uint32_t smem_u32(const void* p) {
    uint32_t a;
    asm("{ .reg .u64 t; cvta.to.shared.u64 t, %1; cvt.u32.u64 %0, t; }" : "=r"(a) : "l"(p));
    return a;
}
__device__ __forceinline__ void cpasync16(uint32_t dst, const void* src) {
    asm volatile("cp.async.cg.shared.global [%0], [%1], 16;" :: "r"(dst), "l"(src));
}
#define CP_COMMIT() asm volatile("cp.async.commit_group;" ::: "memory")
#define CP_WAIT(n)  asm volatile("cp.async.wait_group %0;" :: "n"(n) : "memory")

#define MMA16(C, A0, A1, A2, A3, B0, B1) \
    asm volatile("mma.sync.aligned.m16n8k16.row.col.f32.f16.f16.f32 " \
        "{%0,%1,%2,%3}, {%4,%5,%6,%7}, {%8,%9}, {%0,%1,%2,%3};" \
        : "+f"((C)[0]), "+f"((C)[1]), "+f"((C)[2]), "+f"((C)[3]) \
        : "r"(A0), "r"(A1), "r"(A2), "r"(A3), "r"(B0), "r"(B1))

// ---------------- prep: pack codebook splits (positive) + half-norms ----------------
__global__ void rvq_prep(const float* __restrict__ cb) {
    int e = blockIdx.x * blockDim.x + threadIdx.x;
    if (e >= LL * NEC) return;
    const float* row = cb + (size_t)e * DD;
    __half h[DD], lo[DD];
    float cn = 0.f;
    #pragma unroll
    for (int k = 0; k < DD; k++) {
        float v = row[k];
        sp16(v, h[k], lo[k]);
        cn = fmaf(v, v, cn);
    }
    g_cn[e] = 0.5f * cn;
    uint32_t* dst = g_bp + (size_t)e * 32;
    #pragma unroll
    for (int kk = 0; kk < 4; kk++) {
        dst[8*kk + 0] = packh2(h[2*kk],       h[2*kk + 1]);
        dst[8*kk + 1] = packh2(h[2*kk + 8],   h[2*kk + 9]);
        dst[8*kk + 2] = packh2(h[16 + 2*kk],  h[16 + 2*kk + 1]);
        dst[8*kk + 3] = packh2(h[24 + 2*kk],  h[24 + 2*kk + 1]);
        dst[8*kk + 4] = packh2(lo[2*kk],      lo[2*kk + 1]);
        dst[8*kk + 5] = packh2(lo[2*kk + 8],  lo[2*kk + 9]);
        dst[8*kk + 6] = packh2(lo[16 + 2*kk], lo[16 + 2*kk + 1]);
        dst[8*kk + 7] = packh2(lo[24 + 2*kk], lo[24 + 2*kk + 1]);
    }
}

// ---------------- main ----------------
__global__ void __launch_bounds__(TM, 4) rvq_mma_kernel(
    const float* __restrict__ x, const float* __restrict__ cb,
    float* __restrict__ out, int N, int has_loss, int has_idx, int nblk)
{
    extern __shared__ char smem[];
    const uint32_t sbase = smem_u32(smem);
    const int tid = threadIdx.x;
    const int w = tid >> 5;
    const int lane = tid & 31;
    const int q = lane >> 2;
    const int kk = lane & 3;
    const int p = blockIdx.x * TM + tid;
    const bool active = (p < N);

    char* rrow = smem + OFF_R + tid * 144;

    // init residual rows
    {
        float4* rp = (float4*)rrow;
        if (active) {
            const float4* xr = (const float4*)(x + (size_t)p * DD);
            #pragma unroll
            for (int j = 0; j < 8; j++) rp[j] = xr[j];
        } else {
            float4 z = make_float4(0.f, 0.f, 0.f, 0.f);
            #pragma unroll
            for (int j = 0; j < 8; j++) rp[j] = z;
        }
    }

    // swizzled B read offsets for this thread (within a code row)
    const uint32_t bhOff = OFF_B + (uint32_t)q * 128 + (uint32_t)(((2*kk)     ^ q) * 16);
    const uint32_t blOff = OFF_B + (uint32_t)q * 128 + (uint32_t)(((2*kk + 1) ^ q) * 16);

    float tl[LL];
    int bia[LL];

    for (int l = 0; l < LL; l++) {
        __syncthreads();   // entry: ALL warps done reading previous B

        // ---- phase1: cp.async codes 0..111 (+ cn); doesn't touch A region ----
        {
            const char* src = (const char*)(g_bp + (size_t)(l * 256) * 32);
            #pragma unroll
            for (int i = tid; i < 896; i += TM) {
                int code = i >> 3, c = i & 7;
                cpasync16(sbase + OFF_B + code * 128 + ((c ^ (code & 7)) * 16), src + (size_t)i * 16);
            }
            const char* csrc = (const char*)(g_cn + (size_t)l * 256);
            if (tid < 64) cpasync16(sbase + OFF_CN + tid * 16, csrc + (size_t)tid * 16);
            CP_COMMIT();
        }

        // ---- A = -residual fp16 splits -> OFF_A (warp-local rows) ----
        {
            float t[DD];
            const float4* rp = (const float4*)rrow;
            #pragma unroll
            for (int j = 0; j < 8; j++) {
                float4 v = rp[j];
                t[4*j] = v.x; t[4*j+1] = v.y; t[4*j+2] = v.z; t[4*j+3] = v.w;
            }
            char* ap = smem + OFF_A + tid * 144;
            #pragma unroll
            for (int c4 = 0; c4 < 4; c4++) {
                __half h0,l0,h1,l1,h2,l2,h3,l3,h4,l4,h5,l5,h6,l6,h7,l7;
                sp16(-t[2*c4],        h0, l0); sp16(-t[2*c4 + 1],      h1, l1);
                sp16(-t[2*c4 + 8],    h2, l2); sp16(-t[2*c4 + 9],      h3, l3);
                sp16(-t[16 + 2*c4],   h4, l4); sp16(-t[16 + 2*c4 + 1], h5, l5);
                sp16(-t[24 + 2*c4],   h6, l6); sp16(-t[24 + 2*c4 + 1], h7, l7);
                *(uint4*)(ap + c4 * 16)      = make_uint4(packh2(h0,h1), packh2(h2,h3), packh2(h4,h5), packh2(h6,h7));
                *(uint4*)(ap + 64 + c4 * 16) = make_uint4(packh2(l0,l1), packh2(l2,l3), packh2(l4,l5), packh2(l6,l7));
            }
        }
        __syncwarp();      // warp's A rows visible to warp's own frag loads

        // ---- A fragments (resident for the layer); reads ONLY this warp's rows ----
        uint4 U0h[2], U1h[2], U0l[2], U1l[2];
        {
            const char* ab = smem + OFF_A + (size_t)(w * 32 + q) * 144 + kk * 16;
            #pragma unroll
            for (int m = 0; m < 2; m++) {
                U0h[m] = *(const uint4*)(ab + (m * 16) * 144);
                U1h[m] = *(const uint4*)(ab + (m * 16 + 8) * 144);
                U0l[m] = *(const uint4*)(ab + (m * 16) * 144 + 64);
                U1l[m] = *(const uint4*)(ab + (m * 16 + 8) * 144 + 64);
            }
        }
        __syncwarp();      // all lanes done reading A -> warp's A area reusable

        // ---- phase2: each warp restages EXACTLY the 36 codes aliasing ITS OWN A rows ----
        {
            const char* src = (const char*)(g_bp + (size_t)(l * 256) * 32);
            int base = 896 + 288 * w + lane;
            #pragma unroll
            for (int t = 0; t < 9; t++) {
                int i = base + 32 * t;
                int code = i >> 3, c = i & 7;
                cpasync16(sbase + OFF_B + code * 128 + ((c ^ (code & 7)) * 16), src + (size_t)i * 16);
            }
            CP_COMMIT();
        }

        float best[4];
        int bidx[4];
        #pragma unroll
        for (int j = 0; j < 4; j++) { best[j] = 3.402823466e38f; bidx[j] = 0; }

        auto compute_range = [&](int nt2_lo, int nt2_hi) {
            #pragma unroll 2
            for (int nt2 = nt2_lo; nt2 < nt2_hi; nt2++) {
                const char* p0 = smem + (size_t)nt2 * 2048;
                uint4 BH0 = *(const uint4*)(p0 + bhOff);
                uint4 BL0 = *(const uint4*)(p0 + blOff);
                uint4 BH1 = *(const uint4*)(p0 + 1024 + bhOff);
                uint4 BL1 = *(const uint4*)(p0 + 1024 + blOff);
                float2 cn0 = *(const float2*)(smem + OFF_CN + (size_t)(nt2 * 16 + kk * 2) * 4);
                float2 cn1 = *(const float2*)(smem + OFF_CN + (size_t)(nt2 * 16 + 8 + kk * 2) * 4);

                float C0[2][4], C1[2][4];
                #pragma unroll
                for (int m = 0; m < 2; m++) {
                    C0[m][0] = cn0.x; C0[m][1] = cn0.y; C0[m][2] = cn0.x; C0[m][3] = cn0.y;
                    C1[m][0] = cn1.x; C1[m][1] = cn1.y; C1[m][2] = cn1.x; C1[m][3] = cn1.y;
                }
                #pragma unroll
                for (int m = 0; m < 2; m++) {
                    MMA16(C0[m], U0h[m].x, U1h[m].x, U0h[m].y, U1h[m].y, BH0.x, BH0.y);
                    MMA16(C1[m], U0h[m].x, U1h[m].x, U0h[m].y, U1h[m].y, BH1.x, BH1.y);
                }
                #pragma unroll
                for (int m = 0; m < 2; m++) {
                    MMA16(C0[m], U0h[m].z, U1h[m].z, U0h[m].w, U1h[m].w, BH0.z, BH0.w);
                    MMA16(C1[m], U0h[m].z, U1h[m].z, U0h[m].w, U1h[m].w, BH1.z, BH1.w);
                }
                #pragma unroll
                for (int m = 0; m < 2; m++) {
                    MMA16(C0[m], U0l[m].x, U1l[m].x, U0l[m].y, U1l[m].y, BH0.x, BH0.y);
                    MMA16(C1[m], U0l[m].x, U1l[m].x, U0l[m].y, U1l[m].y, BH1.x, BH1.y);
                }
                #pragma unroll
                for (int m = 0; m < 2; m++) {
                    MMA16(C0[m], U0l[m].z, U1l[m].z, U0l[m].w, U1l[m].w, BH0.z, BH0.w);
                    MMA16(C1[m], U0l[m].z, U1l[m].z, U0l[m].w, U1l[m].w, BH1.z, BH1.w);
                }
                #pragma unroll
                for (int m = 0; m < 2; m++) {
                    MMA16(C0[m], U0h[m].x, U1h[m].x, U0h[m].y, U1h[m].y, BL0.x, BL0.y);
                    MMA16(C1[m], U0h[m].x, U1h[m].x, U0h[m].y, U1h[m].y, BL1.x, BL1.y);
                }
                #pragma unroll
                for (int m = 0; m < 2; m++) {
                    MMA16(C0[m], U0h[m].z, U1h[m].z, U0h[m].w, U1h[m].w, BL0.z, BL0.w);
                    MMA16(C1[m], U0h[m].z, U1h[m].z, U0h[m].w, U1h[m].w, BL1.z, BL1.w);
                }

                int nb0 = (nt2 * 16) + kk * 2;
                int nb1 = nb0 + 8;
                #pragma unroll
                for (int m = 0; m < 2; m++)
                    #pragma unroll
                    for (int hi = 0; hi < 2; hi++) {
                        int jj = m * 2 + hi;
                        {
                            float c0 = C0[m][hi*2], c1 = C0[m][hi*2 + 1];
                            float mn = fminf(c0, c1);
                            int cand = (c1 < c0) ? (nb0 + 1) : nb0;
                            bidx[jj] = (mn < best[jj]) ? cand : bidx[jj];
                            best[jj] = fminf(best[jj], mn);
                        }
                        {
                            float c0 = C1[m][hi*2], c1 = C1[m][hi*2 + 1];
                            float mn = fminf(c0, c1);
                            int cand = (c1 < c0) ? (nb1 + 1) : nb1;
                            bidx[jj] = (mn < best[jj]) ? cand : bidx[jj];
                            best[jj] = fminf(best[jj], mn);
                        }
                    }
            }
        };

        // ---- split-wait: compute codes 0..111 while phase2 lands ----
        CP_WAIT(1);        // phase1 (codes 0..111 + cn) done
        __syncthreads();   // visible to all warps
        compute_range(0, 7);

        CP_WAIT(0);        // phase2 (codes 112..255) done (landed under compute above)
        __syncthreads();
        compute_range(7, 16);

        // ---- argmin reduce across the 4 kk-lanes of each group ----
        #pragma unroll
        for (int jj = 0; jj < 4; jj++) {
            #pragma unroll
            for (int ofs = 1; ofs <= 2; ofs <<= 1) {
                float ob = __shfl_xor_sync(0xffffffffu, best[jj], ofs);
                int oi = __shfl_xor_sync(0xffffffffu, bidx[jj], ofs);
                if (ob < best[jj] || (ob == best[jj] && oi < bidx[jj])) {
                    best[jj] = ob; bidx[jj] = oi;
                }
            }
        }
        int* argb = (int*)(smem + OFF_ARG);
        if (kk == 0) {
            #pragma unroll
            for (int jj = 0; jj < 4; jj++)
                argb[w * 32 + (jj >> 1) * 16 + (jj & 1) * 8 + q] = bidx[jj];
        }
        __syncwarp();
        int bi = argb[w * 32 + lane];
        bia[l] = bi;

        // ---- residual update + loss; code vector gathered from SMEM (c = h + l) ----
        {
            const char* crow = smem + OFF_B + (size_t)bi * 128;
            const int sw = bi & 7;
            float t[DD];
            {
                const float4* rp = (const float4*)rrow;
                #pragma unroll
                for (int j = 0; j < 8; j++) {
                    float4 v = rp[j];
                    t[4*j] = v.x; t[4*j+1] = v.y; t[4*j+2] = v.z; t[4*j+3] = v.w;
                }
            }
            float ls = 0.f;
            #pragma unroll
            for (int kkc = 0; kkc < 4; kkc++) {
                uint4 H = *(const uint4*)(crow + (((2*kkc)     ^ sw) * 16));
                uint4 L = *(const uint4*)(crow + (((2*kkc + 1) ^ sw) * 16));
                const uint32_t hw[4] = {H.x, H.y, H.z, H.w};
                const uint32_t lw[4] = {L.x, L.y, L.z, L.w};
                const int baseix[4] = {2*kkc, 2*kkc + 8, 16 + 2*kkc, 24 + 2*kkc};
                #pragma unroll
                for (int t2 = 0; t2 < 4; t2++) {
                    float2 hf = __half22float2(*(const __half2*)&hw[t2]);
                    float2 lf = __half22float2(*(const __half2*)&lw[t2]);
                    float cx = hf.x + lf.x;
                    float cy = hf.y + lf.y;
                    int b0 = baseix[t2];
                    float t0, xres;
                    t0 = cx - t[b0];     ls = fmaf(t0, t0, ls); xres = t[b0]     + t0; t[b0]     = t[b0]     - xres;
                    t0 = cy - t[b0 + 1]; ls = fmaf(t0, t0, ls); xres = t[b0 + 1] + t0; t[b0 + 1] = t[b0 + 1] - xres;
                }
            }
            {
                float4* rp = (float4*)rrow;
                #pragma unroll
                for (int j = 0; j < 8; j++)
                    rp[j] = make_float4(t[4*j], t[4*j+1], t[4*j+2], t[4*j+3]);
            }
            tl[l] = active ? ls : 0.f;
        }
    }

    // ---- outputs ----
    if (active) {
        const float4* xr = (const float4*)(x + (size_t)p * DD);
        float4* qo = (float4*)(out + (size_t)p * DD);
        const float4* rp = (const float4*)rrow;
        #pragma unroll
        for (int j = 0; j < 8; j++) {
            float4 v = xr[j];
            float4 rv = rp[j];
            float4 qv;
            qv.x = v.x - rv.x; qv.y = v.y - rv.y;
            qv.z = v.z - rv.z; qv.w = v.w - rv.w;
            qo[j] = qv;
        }
        if (has_idx) {
            float* oi = out + (size_t)N * DD + (has_loss ? 1 : 0) + (size_t)p * LL;
            #pragma unroll
            for (int l = 0; l < LL; l++) oi[l] = (float)bia[l];
        }
    }

    // ---- per-block loss partials: warp shuffle reduce (deterministic order) ----
    {
        float* wsum = (float*)(smem + OFF_RED);
        #pragma unroll
        for (int l = 0; l < LL; l++) {
            float v = tl[l];
            v += __shfl_xor_sync(0xffffffffu, v, 16);
            v += __shfl_xor_sync(0xffffffffu, v, 8);
            v += __shfl_xor_sync(0xffffffffu, v, 4);
            v += __shfl_xor_sync(0xffffffffu, v, 2);
            v += __shfl_xor_sync(0xffffffffu, v, 1);
            if (lane == 0) wsum[w * LL + l] = v;
        }
        __syncthreads();
        if (tid < LL) {
            float s = ((wsum[tid] + wsum[LL + tid]) + (wsum[2*LL + tid] + wsum[3*LL + tid]));
            g_part[(size_t)blockIdx.x * LL + tid] = s;
        }
        __threadfence();
        __syncthreads();
    }

    // ---- last block finalizes loss, resets ctr ----
    unsigned* flag = (unsigned*)(smem + OFF_FLAG);
    if (tid == 0) {
        unsigned done = atomicAdd(&g_ctr, 1u);
        *flag = (done == (unsigned)(nblk - 1)) ? 1u : 0u;
    }
    __syncthreads();
    if (*flag) {
        __threadfence();
        double acc = 0.0;
        for (int b = tid; b < nblk; b += TM) {
            #pragma unroll
            for (int l = 0; l < LL; l++) acc += (double)g_part[(size_t)b * LL + l];
        }
        double* dred = (double*)(smem + OFF_RED);
        dred[tid] = acc;
        __syncthreads();
        #pragma unroll
        for (int s = TM / 2; s > 0; s >>= 1) {
            if (tid < s) dred[tid] += dred[tid + s];
            __syncthreads();
        }
        if (tid == 0) {
            if (has_loss) {
                double wgt = (1.0 + (double)RVQ_BETA) / ((double)N * (double)DD * (double)LL);
                out[(size_t)N * DD] = (float)(dred[0] * wgt);
            }
            g_ctr = 0u;
        }
    }
}

extern "C" void kernel_launch(void* const* d_in, const int* in_sizes, int n_in,
                              void* d_out, int out_size) {
    const float* x;
    const float* cb;
    int nx;
    if (n_in >= 2 && in_sizes[0] >= in_sizes[1]) {
        x = (const float*)d_in[0]; cb = (const float*)d_in[1]; nx = in_sizes[0];
    } else {
        x = (const float*)d_in[1]; cb = (const float*)d_in[0]; nx = in_sizes[1];
    }
    int N = nx / DD;
    float* out = (float*)d_out;

    long long need_full = (long long)N * DD + 1 + (long long)N * LL;
    int has_loss = (out_size > (long long)N * DD) ? 1 : 0;
    int has_idx  = (out_size >= need_full) ? 1 : 0;

    int nblk = (N + TM - 1) / TM;
    if (nblk > MAXBLK_P) nblk = MAXBLK_P;

    cudaFuncSetAttribute(rvq_mma_kernel, cudaFuncAttributeMaxDynamicSharedMemorySize, SMEM_BYTES);

    rvq_prep<<<(LL * NEC + 127) / 128, 128>>>(cb);
    rvq_mma_kernel<<<nblk, TM, SMEM_BYTES>>>(x, cb, out, N, has_loss, has_idx, nblk);
}

// round 12
// speedup vs baseline: 1.0770x; 1.0110x over previous
#include <cuda_runtime.h>
#include <cuda_fp16.h>
#include <cstdint>
#include <cstddef>

// ResidualVectorQuantizer via warp-level fp16 MMA, 3-term exact-enough fp32 GEMM.
// R12: R11 base (117.3us) + one-shot start stagger to desynchronize co-resident
//      blocks (their per-layer serial phases currently coincide, idling tensor).
// N x D points, L layers of NE codes (D=32, NE=256, L=4).
// Out (float32): x_q [N*D], mean_loss [1], indices [N*L].

#define DD   32
#define NEC  256
#define LL   4
#define TM   128
#define RVQ_BETA 0.25f
#define MAXBLK_P 8192

// ---- global scratch ----
__device__ uint32_t g_bp[LL * NEC * 32];
__device__ float    g_cn[LL * NEC];          // 0.5*||c||^2
__device__ float    g_part[MAXBLK_P * LL];
__device__ unsigned g_ctr;

// ---- smem map (bytes) ----
#define OFF_B    0          // 256 codes * 128B swizzled = 32768
#define OFF_A    14336      // A rows alias B codes 112..255 (warp-local partition)
#define OFF_R    32768      // residual 128*144 = 18432
#define OFF_CN   51200      // 1024
#define OFF_ARG  52224      // 512
#define OFF_RED  52736      // 1024
#define OFF_FLAG 53760
#define SMEM_BYTES 53888

__device__ __forceinline__ uint32_t packh2(__half a, __half b) {
    __half2 h = __halves2half2(a, b);
    return *(uint32_t*)&h;
}
__device__ __forceinline__ void sp16(float v, __half& h, __half& l) {
    h = __float2half_rn(v);
    l = __float2half_rn(v - __half2float(h));
}
__device__ __forceinline__ uint32_t smem_u32(const void* p) {
    uint32_t a;
    asm("{ .reg .u64 t; cvta.to.shared.u64 t, %1; cvt.u32.u64 %0, t; }" : "=r"(a) : "l"(p));
    return a;
}
__device__ __forceinline__ void cpasync16(uint32_t dst, const void* src) {
    asm volatile("cp.async.cg.shared.global [%0], [%1], 16;" :: "r"(dst), "l"(src));
}
#define CP_COMMIT() asm volatile("cp.async.commit_group;" ::: "memory")
#define CP_WAIT(n)  asm volatile("cp.async.wait_group %0;" :: "n"(n) : "memory")

#define MMA16(C, A0, A1, A2, A3, B0, B1) \
    asm volatile("mma.sync.aligned.m16n8k16.row.col.f32.f16.f16.f32 " \
        "{%0,%1,%2,%3}, {%4,%5,%6,%7}, {%8,%9}, {%0,%1,%2,%3};" \
        : "+f"((C)[0]), "+f"((C)[1]), "+f"((C)[2]), "+f"((C)[3]) \
        : "r"(A0), "r"(A1), "r"(A2), "r"(A3), "r"(B0), "r"(B1))

// ---------------- prep ----------------
__global__ void rvq_prep(const float* __restrict__ cb) {
    int e = blockIdx.x * blockDim.x + threadIdx.x;
    if (e >= LL * NEC) return;
    const float* row = cb + (size_t)e * DD;
    __half h[DD], lo[DD];
    float cn = 0.f;
    #pragma unroll
    for (int k = 0; k < DD; k++) {
        float v = row[k];
        sp16(v, h[k], lo[k]);
        cn = fmaf(v, v, cn);
    }
    g_cn[e] = 0.5f * cn;
    uint32_t* dst = g_bp + (size_t)e * 32;
    #pragma unroll
    for (int kk = 0; kk < 4; kk++) {
        dst[8*kk + 0] = packh2(h[2*kk],       h[2*kk + 1]);
        dst[8*kk + 1] = packh2(h[2*kk + 8],   h[2*kk + 9]);
        dst[8*kk + 2] = packh2(h[16 + 2*kk],  h[16 + 2*kk + 1]);
        dst[8*kk + 3] = packh2(h[24 + 2*kk],  h[24 + 2*kk + 1]);
        dst[8*kk + 4] = packh2(lo[2*kk],      lo[2*kk + 1]);
        dst[8*kk + 5] = packh2(lo[2*kk + 8],  lo[2*kk + 9]);
        dst[8*kk + 6] = packh2(lo[16 + 2*kk], lo[16 + 2*kk + 1]);
        dst[8*kk + 7] = packh2(lo[24 + 2*kk], lo[24 + 2*kk + 1]);
    }
}

// ---------------- main ----------------
__global__ void __launch_bounds__(TM, 4) rvq_mma_kernel(
    const float* __restrict__ x, const float* __restrict__ cb,
    float* __restrict__ out, int N, int has_loss, int has_idx, int nblk)
{
    extern __shared__ char smem[];
    const uint32_t sbase = smem_u32(smem);
    const int tid = threadIdx.x;
    const int w = tid >> 5;
    const int lane = tid & 31;
    const int q = lane >> 2;
    const int kk = lane & 3;
    const int p = blockIdx.x * TM + tid;
    const bool active = (p < N);

    // ---- one-shot start stagger: desynchronize co-resident blocks ----
    // Co-resident blocks on an SM have bids ~148 apart; give them phases
    // 0/4K/8K/12K cycles so per-layer serial phases interleave, not coincide.
    {
        unsigned phase = (blockIdx.x / 148) & 3u;
        if (phase) {
            unsigned long long tgt = (unsigned long long)phase * 4096ull;
            unsigned long long t0 = clock64();
            while ((unsigned long long)(clock64() - t0) < tgt) { }
        }
    }

    char* rrow = smem + OFF_R + tid * 144;

    // init residual rows
    {
        float4* rp = (float4*)rrow;
        if (active) {
            const float4* xr = (const float4*)(x + (size_t)p * DD);
            #pragma unroll
            for (int j = 0; j < 8; j++) rp[j] = xr[j];
        } else {
            float4 z = make_float4(0.f, 0.f, 0.f, 0.f);
            #pragma unroll
            for (int j = 0; j < 8; j++) rp[j] = z;
        }
    }

    const uint32_t bhOff = OFF_B + (uint32_t)q * 128 + (uint32_t)(((2*kk)     ^ q) * 16);
    const uint32_t blOff = OFF_B + (uint32_t)q * 128 + (uint32_t)(((2*kk + 1) ^ q) * 16);

    float tl[LL];
    int bia[LL];

    for (int l = 0; l < LL; l++) {
        __syncthreads();   // entry: ALL warps done reading previous B

        // ---- phase1: cp.async codes 0..111 (+ cn); doesn't touch A region ----
        {
            const char* src = (const char*)(g_bp + (size_t)(l * 256) * 32);
            #pragma unroll
            for (int i = tid; i < 896; i += TM) {
                int code = i >> 3, c = i & 7;
                cpasync16(sbase + OFF_B + code * 128 + ((c ^ (code & 7)) * 16), src + (size_t)i * 16);
            }
            const char* csrc = (const char*)(g_cn + (size_t)l * 256);
            if (tid < 64) cpasync16(sbase + OFF_CN + tid * 16, csrc + (size_t)tid * 16);
            CP_COMMIT();
        }

        // ---- A = -residual fp16 splits -> OFF_A (warp-local rows) ----
        {
            float t[DD];
            const float4* rp = (const float4*)rrow;
            #pragma unroll
            for (int j = 0; j < 8; j++) {
                float4 v = rp[j];
                t[4*j] = v.x; t[4*j+1] = v.y; t[4*j+2] = v.z; t[4*j+3] = v.w;
            }
            char* ap = smem + OFF_A + tid * 144;
            #pragma unroll
            for (int c4 = 0; c4 < 4; c4++) {
                __half h0,l0,h1,l1,h2,l2,h3,l3,h4,l4,h5,l5,h6,l6,h7,l7;
                sp16(-t[2*c4],        h0, l0); sp16(-t[2*c4 + 1],      h1, l1);
                sp16(-t[2*c4 + 8],    h2, l2); sp16(-t[2*c4 + 9],      h3, l3);
                sp16(-t[16 + 2*c4],   h4, l4); sp16(-t[16 + 2*c4 + 1], h5, l5);
                sp16(-t[24 + 2*c4],   h6, l6); sp16(-t[24 + 2*c4 + 1], h7, l7);
                *(uint4*)(ap + c4 * 16)      = make_uint4(packh2(h0,h1), packh2(h2,h3), packh2(h4,h5), packh2(h6,h7));
                *(uint4*)(ap + 64 + c4 * 16) = make_uint4(packh2(l0,l1), packh2(l2,l3), packh2(l4,l5), packh2(l6,l7));
            }
        }
        __syncwarp();

        // ---- A fragments (resident for the layer) ----
        uint4 U0h[2], U1h[2], U0l[2], U1l[2];
        {
            const char* ab = smem + OFF_A + (size_t)(w * 32 + q) * 144 + kk * 16;
            #pragma unroll
            for (int m = 0; m < 2; m++) {
                U0h[m] = *(const uint4*)(ab + (m * 16) * 144);
                U1h[m] = *(const uint4*)(ab + (m * 16 + 8) * 144);
                U0l[m] = *(const uint4*)(ab + (m * 16) * 144 + 64);
                U1l[m] = *(const uint4*)(ab + (m * 16 + 8) * 144 + 64);
            }
        }
        __syncwarp();      // warp's A area reusable

        // ---- phase2: each warp restages the 36 codes aliasing ITS OWN A rows ----
        {
            const char* src = (const char*)(g_bp + (size_t)(l * 256) * 32);
            int base = 896 + 288 * w + lane;
            #pragma unroll
            for (int t = 0; t < 9; t++) {
                int i = base + 32 * t;
                int code = i >> 3, c = i & 7;
                cpasync16(sbase + OFF_B + code * 128 + ((c ^ (code & 7)) * 16), src + (size_t)i * 16);
            }
            CP_COMMIT();
        }

        float best[4];
        int bidx[4];
        #pragma unroll
        for (int j = 0; j < 4; j++) { best[j] = 3.402823466e38f; bidx[j] = 0; }

        auto compute_range = [&](int nt2_lo, int nt2_hi) {
            #pragma unroll 2
            for (int nt2 = nt2_lo; nt2 < nt2_hi; nt2++) {
                const char* p0 = smem + (size_t)nt2 * 2048;
                uint4 BH0 = *(const uint4*)(p0 + bhOff);
                uint4 BL0 = *(const uint4*)(p0 + blOff);
                uint4 BH1 = *(const uint4*)(p0 + 1024 + bhOff);
                uint4 BL1 = *(const uint4*)(p0 + 1024 + blOff);
                float2 cn0 = *(const float2*)(smem + OFF_CN + (size_t)(nt2 * 16 + kk * 2) * 4);
                float2 cn1 = *(const float2*)(smem + OFF_CN + (size_t)(nt2 * 16 + 8 + kk * 2) * 4);

                float C0[2][4], C1[2][4];
                #pragma unroll
                for (int m = 0; m < 2; m++) {
                    C0[m][0] = cn0.x; C0[m][1] = cn0.y; C0[m][2] = cn0.x; C0[m][3] = cn0.y;
                    C1[m][0] = cn1.x; C1[m][1] = cn1.y; C1[m][2] = cn1.x; C1[m][3] = cn1.y;
                }
                #pragma unroll
                for (int m = 0; m < 2; m++) {
                    MMA16(C0[m], U0h[m].x, U1h[m].x, U0h[m].y, U1h[m].y, BH0.x, BH0.y);
                    MMA16(C1[m], U0h[m].x, U1h[m].x, U0h[m].y, U1h[m].y, BH1.x, BH1.y);
                }
                #pragma unroll
                for (int m = 0; m < 2; m++) {
                    MMA16(C0[m], U0h[m].z, U1h[m].z, U0h[m].w, U1h[m].w, BH0.z, BH0.w);
                    MMA16(C1[m], U0h[m].z, U1h[m].z, U0h[m].w, U1h[m].w, BH1.z, BH1.w);
                }
                #pragma unroll
                for (int m = 0; m < 2; m++) {
                    MMA16(C0[m], U0l[m].x, U1l[m].x, U0l[m].y, U1l[m].y, BH0.x, BH0.y);
                    MMA16(C1[m], U0l[m].x, U1l[m].x, U0l[m].y, U1l[m].y, BH1.x, BH1.y);
                }
                #pragma unroll
                for (int m = 0; m < 2; m++) {
                    MMA16(C0[m], U0l[m].z, U1l[m].z, U0l[m].w, U1l[m].w, BH0.z, BH0.w);
                    MMA16(C1[m], U0l[m].z, U1l[m].z, U0l[m].w, U1l[m].w, BH1.z, BH1.w);
                }
                #pragma unroll
                for (int m = 0; m < 2; m++) {
                    MMA16(C0[m], U0h[m].x, U1h[m].x, U0h[m].y, U1h[m].y, BL0.x, BL0.y);
                    MMA16(C1[m], U0h[m].x, U1h[m].x, U0h[m].y, U1h[m].y, BL1.x, BL1.y);
                }
                #pragma unroll
                for (int m = 0; m < 2; m++) {
                    MMA16(C0[m], U0h[m].z, U1h[m].z, U0h[m].w, U1h[m].w, BL0.z, BL0.w);
                    MMA16(C1[m], U0h[m].z, U1h[m].z, U0h[m].w, U1h[m].w, BL1.z, BL1.w);
                }

                int nb0 = (nt2 * 16) + kk * 2;
                int nb1 = nb0 + 8;
                #pragma unroll
                for (int m = 0; m < 2; m++)
                    #pragma unroll
                    for (int hi = 0; hi < 2; hi++) {
                        int jj = m * 2 + hi;
                        {
                            float c0 = C0[m][hi*2], c1 = C0[m][hi*2 + 1];
                            float mn = fminf(c0, c1);
                            int cand = (c1 < c0) ? (nb0 + 1) : nb0;
                            bidx[jj] = (mn < best[jj]) ? cand : bidx[jj];
                            best[jj] = fminf(best[jj], mn);
                        }
                        {
                            float c0 = C1[m][hi*2], c1 = C1[m][hi*2 + 1];
                            float mn = fminf(c0, c1);
                            int cand = (c1 < c0) ? (nb1 + 1) : nb1;
                            bidx[jj] = (mn < best[jj]) ? cand : bidx[jj];
                            best[jj] = fminf(best[jj], mn);
                        }
                    }
            }
        };

        // ---- split-wait: compute codes 0..111 while phase2 lands ----
        CP_WAIT(1);
        __syncthreads();
        compute_range(0, 7);

        CP_WAIT(0);
        __syncthreads();
        compute_range(7, 16);

        // ---- argmin reduce across the 4 kk-lanes of each group ----
        #pragma unroll
        for (int jj = 0; jj < 4; jj++) {
            #pragma unroll
            for (int ofs = 1; ofs <= 2; ofs <<= 1) {
                float ob = __shfl_xor_sync(0xffffffffu, best[jj], ofs);
                int oi = __shfl_xor_sync(0xffffffffu, bidx[jj], ofs);
                if (ob < best[jj] || (ob == best[jj] && oi < bidx[jj])) {
                    best[jj] = ob; bidx[jj] = oi;
                }
            }
        }
        int* argb = (int*)(smem + OFF_ARG);
        if (kk == 0) {
            #pragma unroll
            for (int jj = 0; jj < 4; jj++)
                argb[w * 32 + (jj >> 1) * 16 + (jj & 1) * 8 + q] = bidx[jj];
        }
        __syncwarp();
        int bi = argb[w * 32 + lane];
        bia[l] = bi;

        // ---- residual update + loss; code vector gathered from SMEM (c = h + l) ----
        {
            const char* crow = smem + OFF_B + (size_t)bi * 128;
            const int sw = bi & 7;
            float t[DD];
            {
                const float4* rp = (const float4*)rrow;
                #pragma unroll
                for (int j = 0; j < 8; j++) {
                    float4 v = rp[j];
                    t[4*j] = v.x; t[4*j+1] = v.y; t[4*j+2] = v.z; t[4*j+3] = v.w;
                }
            }
            float ls = 0.f;
            #pragma unroll
            for (int kkc = 0; kkc < 4; kkc++) {
                uint4 H = *(const uint4*)(crow + (((2*kkc)     ^ sw) * 16));
                uint4 L = *(const uint4*)(crow + (((2*kkc + 1) ^ sw) * 16));
                const uint32_t hw[4] = {H.x, H.y, H.z, H.w};
                const uint32_t lw[4] = {L.x, L.y, L.z, L.w};
                const int baseix[4] = {2*kkc, 2*kkc + 8, 16 + 2*kkc, 24 + 2*kkc};
                #pragma unroll
                for (int t2 = 0; t2 < 4; t2++) {
                    float2 hf = __half22float2(*(const __half2*)&hw[t2]);
                    float2 lf = __half22float2(*(const __half2*)&lw[t2]);
                    float cx = hf.x + lf.x;
                    float cy = hf.y + lf.y;
                    int b0 = baseix[t2];
                    float t0, xres;
                    t0 = cx - t[b0];     ls = fmaf(t0, t0, ls); xres = t[b0]     + t0; t[b0]     = t[b0]     - xres;
                    t0 = cy - t[b0 + 1]; ls = fmaf(t0, t0, ls); xres = t[b0 + 1] + t0; t[b0 + 1] = t[b0 + 1] - xres;
                }
            }
            {
                float4* rp = (float4*)rrow;
                #pragma unroll
                for (int j = 0; j < 8; j++)
                    rp[j] = make_float4(t[4*j], t[4*j+1], t[4*j+2], t[4*j+3]);
            }
            tl[l] = active ? ls : 0.f;
        }
    }

    // ---- outputs ----
    if (active) {
        const float4* xr = (const float4*)(x + (size_t)p * DD);
        float4* qo = (float4*)(out + (size_t)p * DD);
        const float4* rp = (const float4*)rrow;
        #pragma unroll
        for (int j = 0; j < 8; j++) {
            float4 v = xr[j];
            float4 rv = rp[j];
            float4 qv;
            qv.x = v.x - rv.x; qv.y = v.y - rv.y;
            qv.z = v.z - rv.z; qv.w = v.w - rv.w;
            qo[j] = qv;
        }
        if (has_idx) {
            float* oi = out + (size_t)N * DD + (has_loss ? 1 : 0) + (size_t)p * LL;
            #pragma unroll
            for (int l = 0; l < LL; l++) oi[l] = (float)bia[l];
        }
    }

    // ---- per-block loss partials: warp shuffle reduce (deterministic order) ----
    {
        float* wsum = (float*)(smem + OFF_RED);
        #pragma unroll
        for (int l = 0; l < LL; l++) {
            float v = tl[l];
            v += __shfl_xor_sync(0xffffffffu, v, 16);
            v += __shfl_xor_sync(0xffffffffu, v, 8);
            v += __shfl_xor_sync(0xffffffffu, v, 4);
            v += __shfl_xor_sync(0xffffffffu, v, 2);
            v += __shfl_xor_sync(0xffffffffu, v, 1);
            if (lane == 0) wsum[w * LL + l] = v;
        }
        __syncthreads();
        if (tid < LL) {
            float s = ((wsum[tid] + wsum[LL + tid]) + (wsum[2*LL + tid] + wsum[3*LL + tid]));
            g_part[(size_t)blockIdx.x * LL + tid] = s;
        }
        __threadfence();
        __syncthreads();
    }

    // ---- last block finalizes loss, resets ctr ----
    unsigned* flag = (unsigned*)(smem + OFF_FLAG);
    if (tid == 0) {
        unsigned done = atomicAdd(&g_ctr, 1u);
        *flag = (done == (unsigned)(nblk - 1)) ? 1u : 0u;
    }
    __syncthreads();
    if (*flag) {
        __threadfence();
        double acc = 0.0;
        for (int b = tid; b < nblk; b += TM) {
            #pragma unroll
            for (int l = 0; l < LL; l++) acc += (double)g_part[(size_t)b * LL + l];
        }
        double* dred = (double*)(smem + OFF_RED);
        dred[tid] = acc;
        __syncthreads();
        #pragma unroll
        for (int s = TM / 2; s > 0; s >>= 1) {
            if (tid < s) dred[tid] += dred[tid + s];
            __syncthreads();
        }
        if (tid == 0) {
            if (has_loss) {
                double wgt = (1.0 + (double)RVQ_BETA) / ((double)N * (double)DD * (double)LL);
                out[(size_t)N * DD] = (float)(dred[0] * wgt);
            }
            g_ctr = 0u;
        }
    }
}

extern "C" void kernel_launch(void* const* d_in, const int* in_sizes, int n_in,
                              void* d_out, int out_size) {
    const float* x;
    const float* cb;
    int nx;
    if (n_in >= 2 && in_sizes[0] >= in_sizes[1]) {
        x = (const float*)d_in[0]; cb = (const float*)d_in[1]; nx = in_sizes[0];
    } else {
        x = (const float*)d_in[1]; cb = (const float*)d_in[0]; nx = in_sizes[1];
    }
    int N = nx / DD;
    float* out = (float*)d_out;

    long long need_full = (long long)N * DD + 1 + (long long)N * LL;
    int has_loss = (out_size > (long long)N * DD) ? 1 : 0;
    int has_idx  = (out_size >= need_full) ? 1 : 0;

    int nblk = (N + TM - 1) / TM;
    if (nblk > MAXBLK_P) nblk = MAXBLK_P;

    cudaFuncSetAttribute(rvq_mma_kernel, cudaFuncAttributeMaxDynamicSharedMemorySize, SMEM_BYTES);

    rvq_prep<<<(LL * NEC + 127) / 128, 128>>>(cb);
    rvq_mma_kernel<<<nblk, TM, SMEM_BYTES>>>(x, cb, out, N, has_loss, has_idx, nblk);
}